// round 16
// baseline (speedup 1.0000x reference)
#include <cuda_runtime.h>
#include <cstdint>
#include <cuda_fp16.h>
#include <mma.h>
#include <math.h>

using namespace nvcuda;

#define NTOK 8192
#define DIM  384
#define NEXP 8
#define HID  1536
#define OUTD 384
#define NPAIR (NTOK * 2)

#define BM 128
#define BN 64
#define KC 64
#define NTHR 256

#define LDA 72
#define LDB 72
#define LDO 68

#define A_STAGE (BM * LDA)               // 9216 halves
#define B_STAGE (KC * LDB)               // 4608 halves
#define STAGE_HALVES (A_STAGE + B_STAGE) // 13824 halves
#define DSM_BYTES (2 * STAGE_HALVES * 2 + 512)

// ---------------- device scratch ----------------
__device__ int     g_counts[NEXP];
__device__ int     g_list[NEXP * NTOK];
__device__ float2  g_gates[NTOK];
__device__ __half  g_x [(size_t)NTOK * DIM];
__device__ __half  g_w1[(size_t)NEXP * DIM * HID];
__device__ __half  g_w2[(size_t)NEXP * HID * OUTD];
__device__ __half  g_h [(size_t)NPAIR * HID];

// ---------------- helpers ----------------
__device__ __forceinline__ void cp16(unsigned smem_dst, const void* gsrc, int srcsize) {
    asm volatile("cp.async.cg.shared.global [%0], [%1], 16, %2;\n"
                 :: "r"(smem_dst), "l"(gsrc), "r"(srcsize) : "memory");
}
__device__ __forceinline__ void cp_commit() {
    asm volatile("cp.async.commit_group;\n" ::: "memory");
}
template<int N>
__device__ __forceinline__ void cp_wait() {
    asm volatile("cp.async.wait_group %0;\n" :: "n"(N) : "memory");
}
__device__ __forceinline__ float gelu_f(float v) {
    return 0.5f * v * (1.0f + erff(v * 0.70710678118654752f));
}

// ---------------- zero counts (must precede setup's router part) ----------
__global__ void zero_counts_kernel() {
    if (threadIdx.x < NEXP) g_counts[threadIdx.x] = 0;
}

// ---------------- merged setup: round x/W1/W2 + router + zero_out ----------
#define N4X (NTOK * DIM / 4)
#define N4W (NEXP * DIM * HID / 4)
#define ROUND_BLKS ((N4X + 2 * N4W) / 256)      // 12288
#define ROUTER_BLKS (NTOK / 8)                  // 1024
#define ZERO_BLKS (NTOK * OUTD / 4 / 256)       // 3072
#define SETUP_BLKS (ROUND_BLKS + ROUTER_BLKS + ZERO_BLKS)

__global__ void setup_kernel(const float* __restrict__ x,
                             const float* __restrict__ Wg,
                             const float* __restrict__ bg,
                             const float* __restrict__ W1,
                             const float* __restrict__ W2,
                             __half* __restrict__ dx,
                             __half* __restrict__ dw1,
                             __half* __restrict__ dw2,
                             float* __restrict__ out) {
    const int bid = blockIdx.x;
    const int tid = threadIdx.x;

    if (bid < ROUND_BLKS) {
        int i = bid * 256 + tid;
        const float* src; __half* dst; int j;
        if (i < N4X)                { src = x;  dst = dx;  j = i; }
        else if (i < N4X + N4W)     { src = W1; dst = dw1; j = i - N4X; }
        else                        { src = W2; dst = dw2; j = i - N4X - N4W; }
        float4 v = ((const float4*)src)[j];
        ((__half2*)dst)[2 * j]     = __floats2half2_rn(v.x, v.y);
        ((__half2*)dst)[2 * j + 1] = __floats2half2_rn(v.z, v.w);
        return;
    }
    if (bid < ROUND_BLKS + ROUTER_BLKS) {
        int warp = (bid - ROUND_BLKS) * 8 + (tid >> 5);
        int lane = tid & 31;

        const float* xr = x + (size_t)warp * DIM;
        float acc[NEXP];
#pragma unroll
        for (int e = 0; e < NEXP; e++) acc[e] = 0.f;
        for (int d = lane; d < DIM; d += 32) {
            float xv = xr[d];
            const float* wr = Wg + d * NEXP;
#pragma unroll
            for (int e = 0; e < NEXP; e++) acc[e] += xv * wr[e];
        }
#pragma unroll
        for (int e = 0; e < NEXP; e++) {
#pragma unroll
            for (int off = 16; off > 0; off >>= 1)
                acc[e] += __shfl_xor_sync(0xffffffffu, acc[e], off);
        }
        if (lane == 0) {
            float v0 = -1e30f, v1 = -1e30f;
            int   i0 = 0,      i1 = 0;
#pragma unroll
            for (int e = 0; e < NEXP; e++) {
                float v = acc[e] + bg[e];
                if (v > v0)      { v1 = v0; i1 = i0; v0 = v; i0 = e; }
                else if (v > v1) { v1 = v;  i1 = e; }
            }
            float e1 = expf(v1 - v0);
            float inv = 1.0f / (1.0f + e1);
            g_gates[warp] = make_float2(inv, e1 * inv);

            int p0 = atomicAdd(&g_counts[i0], 1);
            g_list[i0 * NTOK + p0] = warp * 2;
            int p1 = atomicAdd(&g_counts[i1], 1);
            g_list[i1 * NTOK + p1] = warp * 2 + 1;
        }
        return;
    }
    {
        int i = (bid - ROUND_BLKS - ROUTER_BLKS) * 256 + tid;
        ((float4*)out)[i] = make_float4(0.f, 0.f, 0.f, 0.f);
    }
}

// ---------------- persistent fp16 WMMA grouped GEMM (R11 mainloop) --------
// G1:  h = gelu(gather(g_x) @ g_w1[e] + b1[e]) -> g_h (fp16)
// !G1: out[token] += gate * (gather(g_h) @ g_w2[e] + b2[e])  (2 atomic adds)
template<bool G1>
__global__ __launch_bounds__(NTHR, 3)
void gemm_kernel(const __half* __restrict__ A,
                 const __half* __restrict__ W,
                 const float* __restrict__ bias,
                 void* __restrict__ outv) {
    constexpr int Kd  = G1 ? DIM : HID;
    constexpr int Nd  = G1 ? HID : OUTD;
    constexpr int nk  = Kd / KC;
    constexpr int NMB = NTOK / BM;          // 64
    constexpr int NNB = Nd / BN;            // 24 / 6
    constexpr int NT  = NEXP * NNB * NMB;

    extern __shared__ __align__(16) __half dsm[];
    int* sEntry = (int*)(dsm + 2 * STAGE_HALVES);

    const int tid = threadIdx.x;
    const int w   = tid >> 5;
    const int wm  = (w & 3) * 32;
    const int wn  = (w >> 2) * 32;
    const unsigned smem_u32 = (unsigned)__cvta_generic_to_shared(dsm);

    // per-thread load mapping (tile-invariant parts)
    const int ar = tid >> 1;
    const int ah = (tid & 1) * 32;
    const int br = tid >> 2;
    const int bh = (tid & 3) * 16;

    for (int t = blockIdx.x; t < NT; t += gridDim.x) {
        const int e   = t / (NNB * NMB);
        const int rem = t - e * (NNB * NMB);
        const int n   = rem / NMB;
        const int m   = rem - n * NMB;
        const int M   = g_counts[e];
        const int m0  = m * BM;
        if (m0 >= M) continue;
        const int n0  = n * BN;

        __syncthreads();   // prior tile's epilogue done with sEntry/sOut
        if (tid < BM) {
            int r = m0 + tid;
            sEntry[tid] = (r < M) ? g_list[e * NTOK + r] : -1;
        }
        __syncthreads();

        const __half* We = W + (size_t)e * Kd * Nd;
        const int aentry = sEntry[ar];
        const __half* ag = A + (size_t)(aentry < 0 ? 0 : (G1 ? (aentry >> 1) : aentry)) * Kd + ah;
        const int asz = aentry < 0 ? 0 : 16;
        const __half* bgp = We + (size_t)br * Nd + n0 + bh;

        auto issue = [&](int kc) {
            unsigned s0 = smem_u32 + (unsigned)((kc & 1) * (STAGE_HALVES * 2));
            const __half* ap = ag + kc * KC;
#pragma unroll
            for (int i = 0; i < 4; i++)
                cp16(s0 + (unsigned)((ar * LDA + ah + i * 8) * 2), ap + i * 8, asz);
            unsigned b0 = s0 + (unsigned)(A_STAGE * 2);
            const __half* bp = bgp + (size_t)kc * KC * Nd;
#pragma unroll
            for (int i = 0; i < 2; i++)
                cp16(b0 + (unsigned)((br * LDB + bh + i * 8) * 2), bp + i * 8, 16);
            cp_commit();
        };

        wmma::fragment<wmma::accumulator, 16, 16, 16, float> c[2][2];
#pragma unroll
        for (int i = 0; i < 2; i++)
#pragma unroll
            for (int j = 0; j < 2; j++) wmma::fill_fragment(c[i][j], 0.f);

        issue(0);
        issue(1);

        for (int kc = 0; kc < nk; kc++) {
            if (kc == nk - 1) cp_wait<0>(); else cp_wait<1>();
            __syncthreads();

            const __half* sA = dsm + (kc & 1) * STAGE_HALVES;
            const __half* sB = sA + A_STAGE;
#pragma unroll
            for (int ks = 0; ks < 4; ks++) {
                wmma::fragment<wmma::matrix_a, 16, 16, 16, __half, wmma::row_major> a[2];
                wmma::fragment<wmma::matrix_b, 16, 16, 16, __half, wmma::row_major> b[2];
                wmma::load_matrix_sync(a[0], sA + wm * LDA + ks * 16, LDA);
                wmma::load_matrix_sync(a[1], sA + (wm + 16) * LDA + ks * 16, LDA);
                wmma::load_matrix_sync(b[0], sB + ks * 16 * LDB + wn, LDB);
                wmma::load_matrix_sync(b[1], sB + ks * 16 * LDB + wn + 16, LDB);
#pragma unroll
                for (int i = 0; i < 2; i++) {
                    wmma::mma_sync(c[i][0], a[i], b[0], c[i][0]);
                    wmma::mma_sync(c[i][1], a[i], b[1], c[i][1]);
                }
            }
            __syncthreads();
            if (kc + 2 < nk) issue(kc + 2);
        }

        // ---- epilogue via smem (fp32 view) ----
        float* sOut = (float*)dsm;
#pragma unroll
        for (int i = 0; i < 2; i++)
#pragma unroll
            for (int j = 0; j < 2; j++)
                wmma::store_matrix_sync(sOut + (wm + i * 16) * LDO + wn + j * 16,
                                        c[i][j], LDO, wmma::mem_row_major);
        __syncthreads();

        if (G1) {
            __half* out = (__half*)outv;
            const float* be = bias + e * HID + n0;
            for (int i = tid; i < BM * (BN / 4); i += NTHR) {
                int r = i >> 4, cg = (i & 15) * 4;
                int entry = sEntry[r];
                if (entry >= 0) {
                    float t0 = gelu_f(sOut[r * LDO + cg + 0] + be[cg + 0]);
                    float t1 = gelu_f(sOut[r * LDO + cg + 1] + be[cg + 1]);
                    float t2 = gelu_f(sOut[r * LDO + cg + 2] + be[cg + 2]);
                    float t3 = gelu_f(sOut[r * LDO + cg + 3] + be[cg + 3]);
                    __half2* dst = (__half2*)(out + (size_t)entry * HID + n0 + cg);
                    dst[0] = __floats2half2_rn(t0, t1);
                    dst[1] = __floats2half2_rn(t2, t3);
                }
            }
        } else {
            float* out = (float*)outv;
            const float* be = bias + e * OUTD + n0;
            for (int i = tid; i < BM * BN; i += NTHR) {
                int r = i >> 6, cc = i & 63;
                int entry = sEntry[r];
                if (entry >= 0) {
                    float v = sOut[r * LDO + cc] + be[cc];
                    int tok = entry >> 1;
                    float2 gg = g_gates[tok];
                    float gate = (entry & 1) ? gg.y : gg.x;
                    atomicAdd(out + (size_t)tok * OUTD + n0 + cc, v * gate);
                }
            }
        }
    }
}

// ---------------- launch ----------------
extern "C" void kernel_launch(void* const* d_in, const int* in_sizes, int n_in,
                              void* d_out, int out_size) {
    const float* x  = (const float*)d_in[0];
    const float* Wg = (const float*)d_in[1];
    const float* bg = (const float*)d_in[2];
    const float* W1 = (const float*)d_in[3];
    const float* b1 = (const float*)d_in[4];
    const float* W2 = (const float*)d_in[5];
    const float* b2 = (const float*)d_in[6];
    float* out = (float*)d_out;

    static int nsm = 0;
    if (!nsm) {
        cudaDeviceGetAttribute(&nsm, cudaDevAttrMultiProcessorCount, 0);
        cudaFuncSetAttribute(gemm_kernel<true>,
                             cudaFuncAttributeMaxDynamicSharedMemorySize, DSM_BYTES);
        cudaFuncSetAttribute(gemm_kernel<false>,
                             cudaFuncAttributeMaxDynamicSharedMemorySize, DSM_BYTES);
    }

    __half *gx, *gw1, *gw2, *gh;
    cudaGetSymbolAddress((void**)&gx,  g_x);
    cudaGetSymbolAddress((void**)&gw1, g_w1);
    cudaGetSymbolAddress((void**)&gw2, g_w2);
    cudaGetSymbolAddress((void**)&gh,  g_h);

    zero_counts_kernel<<<1, 32>>>();
    setup_kernel<<<SETUP_BLKS, 256>>>(x, Wg, bg, W1, W2, gx, gw1, gw2, out);
    gemm_kernel<true><<<nsm * 3, NTHR, DSM_BYTES>>>(gx, gw1, b1, gh);
    gemm_kernel<false><<<nsm * 3, NTHR, DSM_BYTES>>>(gh, gw2, b2, out);
}